// round 5
// baseline (speedup 1.0000x reference)
#include <cuda_runtime.h>
#include <math.h>

#define TGT 512
#define BSZ 16
#define EDIM 1024
#define NH 16
#define HD 64
#define NS 32
#define BH 256          // bsz*H
#define MROWS 8192      // tgt*bsz

// ---------------- scratch (device globals: no allocation allowed) ----------
__device__ __align__(16) float g_v[(size_t)BH * TGT * HD];     // V projected (bh,t,d)
__device__ __align__(16) float g_attn[(size_t)BH * TGT * TGT]; // softmax probs
__device__ __align__(16) float g_ao[(size_t)MROWS * EDIM];     // attn out pre-proj (tf32-rounded)
__device__ __align__(16) float g_val[(size_t)MROWS * EDIM];    // value, tf32-rounded
__device__ __align__(16) float g_w0[(size_t)EDIM * EDIM];      // in_proj_weight rounded
__device__ __align__(16) float g_w1[(size_t)EDIM * EDIM];      // out_proj_weight rounded
__device__ int g_mask_flag;                                    // 0=f32, 1=i32, 2=bytes

// ---------------- helpers ---------------------------------------------------
__device__ __forceinline__ unsigned f2tf32(float f) {
    unsigned u;
    asm("cvt.rna.tf32.f32 %0, %1;" : "=r"(u) : "f"(f));
    return u;
}

__device__ __forceinline__ void mma_tf32(float* d, const unsigned* a, const unsigned* b) {
    asm volatile(
        "mma.sync.aligned.m16n8k8.row.col.f32.tf32.tf32.f32 "
        "{%0,%1,%2,%3}, {%4,%5,%6,%7}, {%8,%9}, {%0,%1,%2,%3};"
        : "+f"(d[0]), "+f"(d[1]), "+f"(d[2]), "+f"(d[3])
        : "r"(a[0]), "r"(a[1]), "r"(a[2]), "r"(a[3]), "r"(b[0]), "r"(b[1]));
}

__device__ __forceinline__ void cp_async16(const float* smem_dst, const float* gsrc) {
    unsigned s = (unsigned)__cvta_generic_to_shared(smem_dst);
    asm volatile("cp.async.cg.shared.global [%0], [%1], 16;" :: "r"(s), "l"(gsrc));
}
__device__ __forceinline__ void cp_commit() { asm volatile("cp.async.commit_group;"); }

// ---------------- mask dtype detection ------------------------------------
__global__ void detect_mask_kernel(const unsigned int* __restrict__ m) {
    __shared__ int sf, sb;
    if (threadIdx.x == 0) { sf = 0; sb = 0; }
    __syncthreads();
    int f = 0, bt = 0;
    for (int i = threadIdx.x; i < 4096; i += blockDim.x) {
        unsigned w = m[i];
        if (w == 0x3F800000u) f = 1;
        else if (w & 0xFFFFFF00u) bt = 1;
    }
    if (f)  atomicOr(&sf, 1);
    if (bt) atomicOr(&sb, 1);
    __syncthreads();
    if (threadIdx.x == 0) g_mask_flag = sf ? 0 : (sb ? 2 : 1);
}

// ---------------- tf32 pre-rounding pass -----------------------------------
__global__ void round_tf32_kernel(const float4* __restrict__ src, float4* __restrict__ dst, int n4) {
    int i = blockIdx.x * blockDim.x + threadIdx.x;
    if (i < n4) {
        float4 v = src[i];
        v.x = __uint_as_float(f2tf32(v.x));
        v.y = __uint_as_float(f2tf32(v.y));
        v.z = __uint_as_float(f2tf32(v.z));
        v.w = __uint_as_float(f2tf32(v.w));
        dst[i] = v;
    }
}

// ---------------- fused aw-projection + mask + softmax + avg ---------------
// one block per (b, n). Register-accumulated logits: thread owns m = {tid,
// tid+256}, all 16 heads, via packed f32x2 FMA with {w,w}-paired pos weights.
__global__ void __launch_bounds__(256) attn_kernel(
    const float* __restrict__ adj, const void* __restrict__ maskp,
    const float* __restrict__ posw, const float* __restrict__ posb,
    float* __restrict__ avg_out)
{
    __shared__ float s_log[NH][TGT];                  // 32 KB
    __shared__ float s_mask[TGT];                     // 2 KB
    __shared__ unsigned long long s_pw2[NS][NH];      // 4 KB, {w,w} pairs

    const int tid = threadIdx.x;
    const int b = blockIdx.x >> 9;
    const int n = blockIdx.x & 511;

    // mask row -> additive
    const int flag = g_mask_flag;
    const size_t moff = ((size_t)b * TGT + n) * TGT;
    for (int m = tid; m < TGT; m += 256) {
        bool on;
        if (flag == 0)      on = ((const float*)maskp)[moff + m] != 0.0f;
        else if (flag == 1) on = ((const int*)maskp)[moff + m] != 0;
        else                on = ((const unsigned char*)maskp)[moff + m] != 0;
        s_mask[m] = on ? -1000000.0f : 0.0f;
    }
    // pos weights as packed pairs [s][h]
    for (int i = tid; i < NS * NH; i += 256) {
        int s = i >> 4, h = i & 15;
        float w = posw[h * NS + s];
        unsigned long long p;
        asm("mov.b64 %0, {%1,%2};" : "=l"(p) : "f"(w), "f"(w));
        s_pw2[s][h] = p;
    }
    __syncthreads();

    // logits: acc[h] = packed {l(m0=tid), l(m1=tid+256)}
    unsigned long long acc[NH];
    #pragma unroll
    for (int h = 0; h < NH; h++) acc[h] = 0ULL;

    const float* arow = adj + ((size_t)(b * NS) * TGT + n) * TGT;
    #pragma unroll 4
    for (int s = 0; s < NS; s++) {
        float a0 = __ldcs(arow + (size_t)s * (TGT * TGT) + tid);
        float a1 = __ldcs(arow + (size_t)s * (TGT * TGT) + 256 + tid);
        unsigned long long pa;
        asm("mov.b64 %0, {%1,%2};" : "=l"(pa) : "f"(a0), "f"(a1));
        #pragma unroll
        for (int h = 0; h < NH; h++) {
            unsigned long long w2 = s_pw2[s][h];
            asm("fma.rn.f32x2 %0, %1, %2, %0;" : "+l"(acc[h]) : "l"(pa), "l"(w2));
        }
    }
    #pragma unroll
    for (int h = 0; h < NH; h++) {
        float lo, hi;
        asm("mov.b64 {%0,%1}, %2;" : "=f"(lo), "=f"(hi) : "l"(acc[h]));
        s_log[h][tid] = lo;
        s_log[h][tid + 256] = hi;
    }
    __syncthreads();

    // per-warp softmax: warp w handles heads w, w+8; full row in registers.
    const int lane = tid & 31, w = tid >> 5;
    float msk[16];
    #pragma unroll
    for (int j = 0; j < 16; j++) msk[j] = s_mask[j * 32 + lane];

    #pragma unroll
    for (int hh = 0; hh < 2; hh++) {
        const int h = w + hh * 8;
        const float pb = posb[h];
        float l[16];
        float mx = -3.4e38f;
        #pragma unroll
        for (int j = 0; j < 16; j++) {
            l[j] = s_log[h][j * 32 + lane] + pb + msk[j];
            mx = fmaxf(mx, l[j]);
        }
        #pragma unroll
        for (int o = 16; o; o >>= 1) mx = fmaxf(mx, __shfl_xor_sync(0xFFFFFFFFu, mx, o));
        float sm = 0.0f;
        #pragma unroll
        for (int j = 0; j < 16; j++) { l[j] = __expf(l[j] - mx); sm += l[j]; }
        #pragma unroll
        for (int o = 16; o; o >>= 1) sm += __shfl_xor_sync(0xFFFFFFFFu, sm, o);
        const float inv = 1.0f / sm;
        float* dst = g_attn + ((size_t)(b * NH + h) * TGT + n) * TGT;
        #pragma unroll
        for (int j = 0; j < 16; j++) {
            float p = l[j] * inv;
            dst[j * 32 + lane] = p;
            s_log[h][j * 32 + lane] = p;
        }
    }
    __syncthreads();

    // head-average
    float* av = avg_out + ((size_t)b * TGT + n) * TGT;
    #pragma unroll
    for (int q = 0; q < 2; q++) {
        int m = tid + q * 256;
        float s = 0.0f;
        #pragma unroll
        for (int h = 0; h < NH; h++) s += s_log[h][m];
        av[m] = s * (1.0f / NH);
    }
}

// ---------------- big NT GEMM via TF32 MMA, cp.async double-buffered -------
// C[m,n] = A[m,:]·B[n,:] + bias[n]; M=8192, N=1024, K=1024.
// Inputs are PRE-ROUNDED to tf32-exact f32 -> no cvt in the hot loop.
// MODE 0: A=g_val, scatter C into g_v (bh,t,d). MODE 1: A=g_ao, C=d_out.
template <int MODE>
__global__ void __launch_bounds__(256) gemm_tc_kernel(
    const float* __restrict__ Ain, const float* __restrict__ Bin,
    const float* __restrict__ bias, float* __restrict__ C)
{
    extern __shared__ float dyn[];   // As[2][128][36] then Bs[2][128][36]
    const float* A = (MODE == 0) ? Ain : g_ao;
    const float* B = Bin;

    const int tid = threadIdx.x;
    const int m_blk = blockIdx.y * 128;
    const int n_blk = blockIdx.x * 128;
    const int warp = tid >> 5, lane = tid & 31;
    const int wm = (warp & 1) * 64, wn = (warp >> 1) * 32;
    const int qr = lane >> 2, qc = lane & 3;
    const int srow = tid >> 3;       // 0..31 (+q*32)
    const int sc4  = tid & 7;        // k offset /4

    float d[4][4][4];
    #pragma unroll
    for (int i = 0; i < 4; i++)
        #pragma unroll
        for (int j = 0; j < 4; j++)
            #pragma unroll
            for (int r = 0; r < 4; r++) d[i][j][r] = 0.0f;

    const float* ap = A + (size_t)(m_blk + srow) * 1024 + sc4 * 4;
    const float* bp = B + (size_t)(n_blk + srow) * 1024 + sc4 * 4;

    auto stage = [&](int kt, int buf) {
        float* as = dyn + buf * 4608;
        float* bs = dyn + 9216 + buf * 4608;
        #pragma unroll
        for (int q = 0; q < 4; q++) {
            cp_async16(as + (srow + q * 32) * 36 + sc4 * 4, ap + (size_t)q * 32 * 1024 + kt * 32);
            cp_async16(bs + (srow + q * 32) * 36 + sc4 * 4, bp + (size_t)q * 32 * 1024 + kt * 32);
        }
        cp_commit();
    };

    stage(0, 0);

    for (int kt = 0; kt < 32; kt++) {
        if (kt < 31) {
            stage(kt + 1, (kt + 1) & 1);
            asm volatile("cp.async.wait_group 1;");
        } else {
            asm volatile("cp.async.wait_group 0;");
        }
        __syncthreads();

        const float* as = dyn + (kt & 1) * 4608;
        const float* bs = dyn + 9216 + (kt & 1) * 4608;
        #pragma unroll
        for (int kk = 0; kk < 4; kk++) {
            const int kb = kk * 8;
            unsigned a[4][4], bfr[4][2];
            #pragma unroll
            for (int i = 0; i < 4; i++) {
                a[i][0] = __float_as_uint(as[(wm + i * 16 + qr) * 36 + kb + qc]);
                a[i][1] = __float_as_uint(as[(wm + i * 16 + qr + 8) * 36 + kb + qc]);
                a[i][2] = __float_as_uint(as[(wm + i * 16 + qr) * 36 + kb + qc + 4]);
                a[i][3] = __float_as_uint(as[(wm + i * 16 + qr + 8) * 36 + kb + qc + 4]);
            }
            #pragma unroll
            for (int j = 0; j < 4; j++) {
                bfr[j][0] = __float_as_uint(bs[(wn + j * 8 + qr) * 36 + kb + qc]);
                bfr[j][1] = __float_as_uint(bs[(wn + j * 8 + qr) * 36 + kb + qc + 4]);
            }
            #pragma unroll
            for (int i = 0; i < 4; i++)
                #pragma unroll
                for (int j = 0; j < 4; j++)
                    mma_tf32(d[i][j], a[i], bfr[j]);
        }
        __syncthreads();
    }

    // epilogue: c0(r,c) c1(r,c+1) c2(r+8,c) c3(r+8,c+1)
    #pragma unroll
    for (int i = 0; i < 4; i++) {
        #pragma unroll
        for (int j = 0; j < 4; j++) {
            const int mb = m_blk + wm + i * 16 + qr;
            const int nb = n_blk + wn + j * 8 + qc * 2;
            #pragma unroll
            for (int r = 0; r < 4; r++) {
                const int mi = mb + ((r >= 2) ? 8 : 0);
                const int nj = nb + (r & 1);
                const float v = d[i][j][r] + bias[nj];
                if (MODE == 0) {
                    const int t = mi >> 4, bb = mi & 15;
                    const int h = nj >> 6, dd = nj & 63;
                    g_v[(((size_t)(bb * 16 + h)) * TGT + t) * HD + dd] = v;
                } else {
                    C[(size_t)mi * 1024 + nj] = v;
                }
            }
        }
    }
}

// ---------------- attn @ V via TF32 MMA ------------------------------------
// per bh: O(512x64) = P(512x512) V(512x64). block tile 256x64, 8 warps 64x32.
// epilogue rounds g_ao to tf32-exact so gemm<1> can skip conversion.
__global__ void __launch_bounds__(256) av_tc_kernel() {
    __shared__ unsigned Ps[256][36];
    __shared__ unsigned Vs[32][72];

    const int bh = blockIdx.x >> 1;
    const int t0 = (blockIdx.x & 1) * 256;
    const int b = bh >> 4, h = bh & 15;

    const float* P = g_attn + (size_t)bh * TGT * TGT;
    const float* V = g_v + (size_t)bh * TGT * HD;

    const int tid = threadIdx.x;
    const int warp = tid >> 5, lane = tid & 31;
    const int wm = (warp & 3) * 64, wn = (warp >> 2) * 32;
    const int qr = lane >> 2, qc = lane & 3;

    const int prow = tid >> 3;
    const int pc4  = tid & 7;
    const int vk   = tid >> 4;
    const int vd4  = tid & 15;

    float d[4][4][4];
    #pragma unroll
    for (int i = 0; i < 4; i++)
        #pragma unroll
        for (int j = 0; j < 4; j++)
            #pragma unroll
            for (int r = 0; r < 4; r++) d[i][j][r] = 0.0f;

    for (int k0 = 0; k0 < 512; k0 += 32) {
        #pragma unroll
        for (int q = 0; q < 8; q++) {
            float4 f = *(const float4*)(P + (size_t)(t0 + prow + q * 32) * 512 + k0 + pc4 * 4);
            uint4 u = make_uint4(f2tf32(f.x), f2tf32(f.y), f2tf32(f.z), f2tf32(f.w));
            *(uint4*)&Ps[prow + q * 32][pc4 * 4] = u;
        }
        #pragma unroll
        for (int q = 0; q < 2; q++) {
            float4 f = *(const float4*)(V + (size_t)(k0 + vk + q * 16) * 64 + vd4 * 4);
            uint4 u = make_uint4(f2tf32(f.x), f2tf32(f.y), f2tf32(f.z), f2tf32(f.w));
            *(uint4*)&Vs[vk + q * 16][vd4 * 4] = u;
        }
        __syncthreads();

        #pragma unroll
        for (int kk = 0; kk < 4; kk++) {
            const int kb = kk * 8;
            unsigned a[4][4], bfr[4][2];
            #pragma unroll
            for (int i = 0; i < 4; i++) {
                a[i][0] = Ps[wm + i * 16 + qr][kb + qc];
                a[i][1] = Ps[wm + i * 16 + qr + 8][kb + qc];
                a[i][2] = Ps[wm + i * 16 + qr][kb + qc + 4];
                a[i][3] = Ps[wm + i * 16 + qr + 8][kb + qc + 4];
            }
            #pragma unroll
            for (int j = 0; j < 4; j++) {
                bfr[j][0] = Vs[kb + qc][wn + j * 8 + qr];
                bfr[j][1] = Vs[kb + qc + 4][wn + j * 8 + qr];
            }
            #pragma unroll
            for (int i = 0; i < 4; i++)
                #pragma unroll
                for (int j = 0; j < 4; j++)
                    mma_tf32(d[i][j], a[i], bfr[j]);
        }
        __syncthreads();
    }

    #pragma unroll
    for (int i = 0; i < 4; i++) {
        #pragma unroll
        for (int j = 0; j < 4; j++) {
            const int tb = t0 + wm + i * 16 + qr;
            const int db = wn + j * 8 + qc * 2;
            #pragma unroll
            for (int r = 0; r < 4; r++) {
                const int t = tb + ((r >= 2) ? 8 : 0);
                const int dd = db + (r & 1);
                g_ao[((size_t)t * BSZ + b) * EDIM + h * HD + dd] =
                    __uint_as_float(f2tf32(d[i][j][r]));
            }
        }
    }
}

// ---------------- launch ---------------------------------------------------
extern "C" void kernel_launch(void* const* d_in, const int* in_sizes, int n_in,
                              void* d_out, int out_size) {
    (void)in_sizes; (void)n_in; (void)out_size;
    const float* value = (const float*)d_in[0];
    const float* adj   = (const float*)d_in[1];
    const void*  mask  = d_in[2];
    const float* w_in  = (const float*)d_in[3];
    const float* b_in  = (const float*)d_in[4];
    const float* w_out = (const float*)d_in[5];
    const float* b_out = (const float*)d_in[6];
    const float* posw  = (const float*)d_in[7];
    const float* posb  = (const float*)d_in[8];

    float* out = (float*)d_out;
    float* avg = out + (size_t)TGT * BSZ * EDIM;

    float* d_gval; cudaGetSymbolAddress((void**)&d_gval, g_val);
    float* d_gw0;  cudaGetSymbolAddress((void**)&d_gw0, g_w0);
    float* d_gw1;  cudaGetSymbolAddress((void**)&d_gw1, g_w1);

    detect_mask_kernel<<<1, 256>>>((const unsigned int*)mask);

    // pre-round tf32 inputs
    {
        int n4v = MROWS * EDIM / 4;       // 2,097,152
        int n4w = EDIM * EDIM / 4;        // 262,144
        round_tf32_kernel<<<(n4v + 255) / 256, 256>>>((const float4*)value, (float4*)d_gval, n4v);
        round_tf32_kernel<<<(n4w + 255) / 256, 256>>>((const float4*)w_in,  (float4*)d_gw0, n4w);
        round_tf32_kernel<<<(n4w + 255) / 256, 256>>>((const float4*)w_out, (float4*)d_gw1, n4w);
    }

    constexpr int GSMEM = 4 * 4608 * 4;   // 73,728 B
    cudaFuncSetAttribute((const void*)gemm_tc_kernel<0>,
                         cudaFuncAttributeMaxDynamicSharedMemorySize, GSMEM);
    cudaFuncSetAttribute((const void*)gemm_tc_kernel<1>,
                         cudaFuncAttributeMaxDynamicSharedMemorySize, GSMEM);

    dim3 gg(EDIM / 128, MROWS / 128);
    gemm_tc_kernel<0><<<gg, 256, GSMEM>>>(d_gval, d_gw0, b_in, nullptr);

    attn_kernel<<<BSZ * TGT, 256>>>(adj, mask, posw, posb, avg);

    av_tc_kernel<<<BH * 2, 256>>>();

    gemm_tc_kernel<1><<<gg, 256, GSMEM>>>(nullptr, d_gw1, b_out, out);
}